// round 1
// baseline (speedup 1.0000x reference)
#include <cuda_runtime.h>
#include <math.h>

#define NTOK 4096
#define DMODEL 256
#define NEGV -9e15f
#define SCALEF 0.17677669529663687f  /* 1/sqrt(32) */

// Scratch (allocation-free rule: __device__ globals)
static __device__ float g_q[NTOK * DMODEL];
static __device__ float g_k[NTOK * DMODEL];
static __device__ float g_v[NTOK * DMODEL];
static __device__ float g_att[NTOK * DMODEL];

// ---------------------------------------------------------------------------
// C[M,256] = A[M,256] @ W[256,256] + bias   (M = 4096)
// 64x64 tile, K-step 16, 256 threads, 4x4 register micro-tile.
// ---------------------------------------------------------------------------
__global__ __launch_bounds__(256) void gemm_bias_kernel(
    const float* __restrict__ A, const float* __restrict__ W,
    const float* __restrict__ bias, float* __restrict__ C)
{
    __shared__ float As[16][68];   // [k][m], padded
    __shared__ float Bs[16][68];   // [k][n], padded

    const int tid = threadIdx.x;
    const int tx = tid & 15;
    const int ty = tid >> 4;
    const int mb = blockIdx.x * 64;
    const int nb = blockIdx.y * 64;

    const int arow = tid >> 2;          // 0..63
    const int ac4  = (tid & 3) << 2;    // 0,4,8,12
    const int brow = tid >> 4;          // 0..15
    const int bc4  = (tid & 15) << 2;   // 0..60

    float acc[4][4];
#pragma unroll
    for (int i = 0; i < 4; i++)
#pragma unroll
        for (int j = 0; j < 4; j++) acc[i][j] = 0.f;

    for (int kb = 0; kb < 256; kb += 16) {
        float4 av = *(const float4*)&A[(mb + arow) * 256 + kb + ac4];
        float4 wv = *(const float4*)&W[(kb + brow) * 256 + nb + bc4];
        __syncthreads();
        As[ac4 + 0][arow] = av.x;
        As[ac4 + 1][arow] = av.y;
        As[ac4 + 2][arow] = av.z;
        As[ac4 + 3][arow] = av.w;
        *(float4*)&Bs[brow][bc4] = wv;
        __syncthreads();
#pragma unroll
        for (int kk = 0; kk < 16; kk++) {
            float4 a = *(float4*)&As[kk][ty << 2];
            float4 b = *(float4*)&Bs[kk][tx << 2];
            float a4[4] = {a.x, a.y, a.z, a.w};
            float b4[4] = {b.x, b.y, b.z, b.w};
#pragma unroll
            for (int i = 0; i < 4; i++)
#pragma unroll
                for (int j = 0; j < 4; j++)
                    acc[i][j] += a4[i] * b4[j];
        }
    }

    float4 bv = *(const float4*)&bias[nb + (tx << 2)];
#pragma unroll
    for (int i = 0; i < 4; i++) {
        float4 o;
        o.x = acc[i][0] + bv.x;
        o.y = acc[i][1] + bv.y;
        o.z = acc[i][2] + bv.z;
        o.w = acc[i][3] + bv.w;
        *(float4*)&C[(mb + (ty << 2) + i) * 256 + nb + (tx << 2)] = o;
    }
}

// ---------------------------------------------------------------------------
// Masked flash attention, all 8 heads per query-tile block.
// Block = 128 threads: h = tid&7, qp = tid>>3; thread owns queries qp and qp+16
// of a 32-query tile, for one head (acc = 2 x 32 fp32 in registers).
// Key tile = 32. Online softmax; adj read exactly once overall.
// Per-head chunk rotation ((c+h)&7) keeps k/v LDS.128 bank-conflict-free.
// ---------------------------------------------------------------------------
__global__ __launch_bounds__(128, 2) void attn_kernel(const float* __restrict__ adj)
{
    extern __shared__ float sm[];
    float* q_s = sm;                    // 32 x 264 (padded stride vs q-bank clash)
    float* k_s = sm + 32 * 264;         // 32 x 256
    float* v_s = k_s + 32 * 256;        // 32 x 256
    float* a_s = v_s + 32 * 256;        // 32 x 40 adj tile (padded)

    const int tid = threadIdx.x;
    const int h = tid & 7;
    const int qp = tid >> 3;            // 0..15
    const int q0 = qp;
    const int q1 = qp + 16;
    const int qb = blockIdx.x * 32;
    const int hbase = h << 5;

    // load q tile with per-head chunk rotation
#pragma unroll
    for (int i = 0; i < 16; i++) {
        int idx = tid + (i << 7);       // 0..2047
        int r = idx >> 6;
        int ch = idx & 63;
        int hh = ch >> 3;
        int cc = ch & 7;
        float4 val = *(const float4*)&g_q[(qb + r) * 256 + (ch << 2)];
        *(float4*)&q_s[r * 264 + (hh << 5) + (((cc + hh) & 7) << 2)] = val;
    }

    float acc0[32], acc1[32];
#pragma unroll
    for (int i = 0; i < 32; i++) { acc0[i] = 0.f; acc1[i] = 0.f; }
    float m0 = -INFINITY, m1 = -INFINITY;
    float l0 = 0.f, l1 = 0.f;

    for (int kb = 0; kb < NTOK; kb += 32) {
        __syncthreads();
        // load k/v tiles (rotated) + adj tile
#pragma unroll
        for (int i = 0; i < 16; i++) {
            int idx = tid + (i << 7);
            int r = idx >> 6;
            int ch = idx & 63;
            int hh = ch >> 3;
            int cc = ch & 7;
            int dst = r * 256 + (hh << 5) + (((cc + hh) & 7) << 2);
            int src = (kb + r) * 256 + (ch << 2);
            *(float4*)&k_s[dst] = *(const float4*)&g_k[src];
            *(float4*)&v_s[dst] = *(const float4*)&g_v[src];
        }
#pragma unroll
        for (int i = 0; i < 2; i++) {
            int idx = tid + (i << 7);   // 0..255
            int r = idx >> 3;
            int c4 = (idx & 7) << 2;
            *(float4*)&a_s[r * 40 + c4] =
                *(const float4*)&adj[(qb + r) * NTOK + kb + c4];
        }
        __syncthreads();

        // ----- scores: S = q_h @ k_h^T, 2 queries per thread -----
        float s0[32], s1[32];
#pragma unroll
        for (int j = 0; j < 32; j++) { s0[j] = 0.f; s1[j] = 0.f; }
#pragma unroll
        for (int c = 0; c < 8; c++) {
            int off = hbase + (((c + h) & 7) << 2);
            float4 qa = *(float4*)&q_s[q0 * 264 + off];
            float4 qc = *(float4*)&q_s[q1 * 264 + off];
#pragma unroll
            for (int j = 0; j < 32; j++) {
                float4 kv = *(float4*)&k_s[j * 256 + off];
                s0[j] += qa.x * kv.x; s0[j] += qa.y * kv.y;
                s0[j] += qa.z * kv.z; s0[j] += qa.w * kv.w;
                s1[j] += qc.x * kv.x; s1[j] += qc.y * kv.y;
                s1[j] += qc.z * kv.z; s1[j] += qc.w * kv.w;
            }
        }

        // ----- mask + scale + online softmax -----
        float mx0 = m0, mx1 = m1;
#pragma unroll
        for (int j = 0; j < 32; j++) {
            float e0 = a_s[q0 * 40 + j];
            float e1 = a_s[q1 * 40 + j];
            s0[j] = (e0 > 0.f) ? s0[j] * SCALEF : NEGV;
            s1[j] = (e1 > 0.f) ? s1[j] * SCALEF : NEGV;
            mx0 = fmaxf(mx0, s0[j]);
            mx1 = fmaxf(mx1, s1[j]);
        }
        float corr0 = __expf(m0 - mx0);
        float corr1 = __expf(m1 - mx1);
        m0 = mx0; m1 = mx1;
        float ps0 = 0.f, ps1 = 0.f;
#pragma unroll
        for (int j = 0; j < 32; j++) {
            s0[j] = __expf(s0[j] - mx0);
            s1[j] = __expf(s1[j] - mx1);
            ps0 += s0[j];
            ps1 += s1[j];
        }
        l0 = l0 * corr0 + ps0;
        l1 = l1 * corr1 + ps1;
#pragma unroll
        for (int i = 0; i < 32; i++) { acc0[i] *= corr0; acc1[i] *= corr1; }

        // ----- AV accumulate -----
#pragma unroll
        for (int c = 0; c < 8; c++) {
            int off = hbase + (((c + h) & 7) << 2);
#pragma unroll
            for (int j = 0; j < 32; j++) {
                float4 vv = *(float4*)&v_s[j * 256 + off];
                acc0[(c << 2) + 0] += s0[j] * vv.x;
                acc0[(c << 2) + 1] += s0[j] * vv.y;
                acc0[(c << 2) + 2] += s0[j] * vv.z;
                acc0[(c << 2) + 3] += s0[j] * vv.w;
                acc1[(c << 2) + 0] += s1[j] * vv.x;
                acc1[(c << 2) + 1] += s1[j] * vv.y;
                acc1[(c << 2) + 2] += s1[j] * vv.z;
                acc1[(c << 2) + 3] += s1[j] * vv.w;
            }
        }
    }

    // ----- epilogue: normalize and write (d index = h*32 + c*4 + i) -----
    float inv0 = 1.f / l0;
    float inv1 = 1.f / l1;
#pragma unroll
    for (int c = 0; c < 8; c++) {
        float4 o0, o1;
        o0.x = acc0[(c << 2) + 0] * inv0;
        o0.y = acc0[(c << 2) + 1] * inv0;
        o0.z = acc0[(c << 2) + 2] * inv0;
        o0.w = acc0[(c << 2) + 3] * inv0;
        o1.x = acc1[(c << 2) + 0] * inv1;
        o1.y = acc1[(c << 2) + 1] * inv1;
        o1.z = acc1[(c << 2) + 2] * inv1;
        o1.w = acc1[(c << 2) + 3] * inv1;
        *(float4*)&g_att[(qb + q0) * 256 + hbase + (c << 2)] = o0;
        *(float4*)&g_att[(qb + q1) * 256 + hbase + (c << 2)] = o1;
    }
}

// ---------------------------------------------------------------------------
extern "C" void kernel_launch(void* const* d_in, const int* in_sizes, int n_in,
                              void* d_out, int out_size)
{
    (void)in_sizes; (void)n_in; (void)out_size;
    const float* x   = (const float*)d_in[0];
    const float* adj = (const float*)d_in[1];
    const float* Wq  = (const float*)d_in[2];
    const float* bq  = (const float*)d_in[3];
    const float* Wk  = (const float*)d_in[4];
    const float* bk  = (const float*)d_in[5];
    const float* Wv  = (const float*)d_in[6];
    const float* bv  = (const float*)d_in[7];
    const float* Wo  = (const float*)d_in[8];
    const float* bo  = (const float*)d_in[9];
    float* out = (float*)d_out;

    float *pq, *pk, *pv, *pa;
    cudaGetSymbolAddress((void**)&pq, g_q);
    cudaGetSymbolAddress((void**)&pk, g_k);
    cudaGetSymbolAddress((void**)&pv, g_v);
    cudaGetSymbolAddress((void**)&pa, g_att);

    const int attn_smem = (32 * 264 + 2 * 32 * 256 + 32 * 40) * 4;  // 104448 B
    cudaFuncSetAttribute(attn_kernel,
                         cudaFuncAttributeMaxDynamicSharedMemorySize, attn_smem);

    dim3 gg(64, 4);   // 4096/64 x 256/64
    gemm_bias_kernel<<<gg, 256>>>(x, Wq, bq, pq);
    gemm_bias_kernel<<<gg, 256>>>(x, Wk, bk, pk);
    gemm_bias_kernel<<<gg, 256>>>(x, Wv, bv, pv);
    attn_kernel<<<128, 128, attn_smem>>>(adj);
    gemm_bias_kernel<<<gg, 256>>>(pa, Wo, bo, out);
}

// round 2
// speedup vs baseline: 1.0654x; 1.0654x over previous
#include <cuda_runtime.h>
#include <math.h>

#define NTOK 4096
#define DMODEL 256
#define QSCALE 0.2550760660737454f   /* (1/sqrt(32)) * log2(e) */
#define NEGL2  -1e30f

// Scratch (allocation-free rule: __device__ globals)
static __device__ float g_q[NTOK * DMODEL];
static __device__ float g_k[NTOK * DMODEL];
static __device__ float g_v[NTOK * DMODEL];
static __device__ float g_att[NTOK * DMODEL];

// ---------------- packed f32x2 helpers ----------------
#define FMA2(d, a, b) \
    asm("fma.rn.f32x2 %0, %1, %2, %3;" : "=l"(d) : "l"(a), "l"(b), "l"(d))
#define MUL2(d, a, b) \
    asm("mul.rn.f32x2 %0, %1, %2;" : "=l"(d) : "l"(a), "l"(b))
#define PACK2(d, lo, hi) \
    asm("mov.b64 %0, {%1, %2};" : "=l"(d) : "f"(lo), "f"(hi))

__device__ __forceinline__ float f2_lo(unsigned long long x) {
    return __uint_as_float((unsigned)x);
}
__device__ __forceinline__ float f2_hi(unsigned long long x) {
    return __uint_as_float((unsigned)(x >> 32));
}
__device__ __forceinline__ float ex2(float x) {
    float r;
    asm("ex2.approx.ftz.f32 %0, %1;" : "=f"(r) : "f"(x));
    return r;
}

// ---------------- cp.async helpers ----------------
__device__ __forceinline__ void cp16(float* dst, const float* src) {
    unsigned ds = (unsigned)__cvta_generic_to_shared(dst);
    asm volatile("cp.async.cg.shared.global [%0], [%1], 16;\n" :: "r"(ds), "l"(src));
}
#define CP_COMMIT asm volatile("cp.async.commit_group;\n")
#define CP_WAIT1  asm volatile("cp.async.wait_group 1;\n")
#define CP_WAIT0  asm volatile("cp.async.wait_group 0;\n")

// ---------------------------------------------------------------------------
// C[M,256] = A[M,256] @ W[256,256] + bias   (M = 4096)
// ---------------------------------------------------------------------------
__global__ __launch_bounds__(256) void gemm_bias_kernel(
    const float* __restrict__ A, const float* __restrict__ W,
    const float* __restrict__ bias, float* __restrict__ C)
{
    __shared__ float As[16][68];
    __shared__ float Bs[16][68];

    const int tid = threadIdx.x;
    const int tx = tid & 15;
    const int ty = tid >> 4;
    const int mb = blockIdx.x * 64;
    const int nb = blockIdx.y * 64;

    const int arow = tid >> 2;
    const int ac4  = (tid & 3) << 2;
    const int brow = tid >> 4;
    const int bc4  = (tid & 15) << 2;

    float acc[4][4];
#pragma unroll
    for (int i = 0; i < 4; i++)
#pragma unroll
        for (int j = 0; j < 4; j++) acc[i][j] = 0.f;

    for (int kb = 0; kb < 256; kb += 16) {
        float4 av = *(const float4*)&A[(mb + arow) * 256 + kb + ac4];
        float4 wv = *(const float4*)&W[(kb + brow) * 256 + nb + bc4];
        __syncthreads();
        As[ac4 + 0][arow] = av.x;
        As[ac4 + 1][arow] = av.y;
        As[ac4 + 2][arow] = av.z;
        As[ac4 + 3][arow] = av.w;
        *(float4*)&Bs[brow][bc4] = wv;
        __syncthreads();
#pragma unroll
        for (int kk = 0; kk < 16; kk++) {
            float4 a = *(float4*)&As[kk][ty << 2];
            float4 b = *(float4*)&Bs[kk][tx << 2];
            float a4[4] = {a.x, a.y, a.z, a.w};
            float b4[4] = {b.x, b.y, b.z, b.w};
#pragma unroll
            for (int i = 0; i < 4; i++)
#pragma unroll
                for (int j = 0; j < 4; j++)
                    acc[i][j] += a4[i] * b4[j];
        }
    }

    float4 bv = *(const float4*)&bias[nb + (tx << 2)];
#pragma unroll
    for (int i = 0; i < 4; i++) {
        float4 o;
        o.x = acc[i][0] + bv.x;
        o.y = acc[i][1] + bv.y;
        o.z = acc[i][2] + bv.z;
        o.w = acc[i][3] + bv.w;
        *(float4*)&C[(mb + (ty << 2) + i) * 256 + nb + (tx << 2)] = o;
    }
}

// ---------------------------------------------------------------------------
// Flash attention: block = 32 queries x 8 heads = 256 threads (1 q-head each).
// q lives in registers (packed f32x2, pre-scaled by 1/sqrt(32)*log2e).
// k/v/adj double-buffered via cp.async. Per-head chunk rotation ((c+h)&7)
// keeps all warp-wide LDS.128 conflict-free. Softmax in log2 domain (ex2).
// ---------------------------------------------------------------------------
// smem layout (floats):
//   k buffers: [0, 8192), [8192, 16384)
//   v buffers: [16384, 24576), [24576, 32768)
//   adj buffers (stride 40): [32768, 34048), [34048, 35328)
#define SM_FLOATS 35328

__device__ __forceinline__ void issue_tile(
    int kb, float* ks, float* vs, float* as_,
    const float* gk, const float* gv, const float* __restrict__ adj,
    int qb, int tid)
{
#pragma unroll
    for (int i = 0; i < 8; i++) {
        int idx = tid + (i << 8);      // 0..2047
        int r = idx >> 6;
        int ch = idx & 63;
        int hh = ch >> 3;
        int cc = ch & 7;
        int dst = r * 256 + (hh << 5) + (((cc + hh) & 7) << 2);
        int src = (kb + r) * 256 + (ch << 2);
        cp16(ks + dst, gk + src);
        cp16(vs + dst, gv + src);
    }
    {
        int r = tid >> 3;
        int c4 = (tid & 7) << 2;
        cp16(as_ + r * 40 + c4, adj + (qb + r) * NTOK + kb + c4);
    }
}

__global__ __launch_bounds__(256) void attn_kernel(const float* __restrict__ adj)
{
    extern __shared__ float sm[];
    float* kbuf[2] = { sm,          sm + 8192 };
    float* vbuf[2] = { sm + 16384,  sm + 24576 };
    float* abuf[2] = { sm + 32768,  sm + 34048 };

    const int tid = threadIdx.x;
    const int h = tid & 7;
    const int q = tid >> 3;            // 0..31
    const int qb = blockIdx.x * 32;
    const int hb = h << 5;

    // load + scale + pack q (registers only)
    unsigned long long qpk[16];
    {
        const float* qrow = g_q + (qb + q) * 256 + hb;
#pragma unroll
        for (int c = 0; c < 8; c++) {
            float4 t = *(const float4*)(qrow + (c << 2));
            PACK2(qpk[2 * c],     t.x * QSCALE, t.y * QSCALE);
            PACK2(qpk[2 * c + 1], t.z * QSCALE, t.w * QSCALE);
        }
    }

    unsigned long long acc2[16];
#pragma unroll
    for (int i = 0; i < 16; i++) acc2[i] = 0ull;
    float m = NEGL2, l = 0.f;

    issue_tile(0, kbuf[0], vbuf[0], abuf[0], g_k, g_v, adj, qb, tid);
    CP_COMMIT;

    for (int t = 0; t < 128; t++) {
        const int cur = t & 1;
        if (t < 127) {
            issue_tile((t + 1) << 5, kbuf[cur ^ 1], vbuf[cur ^ 1], abuf[cur ^ 1],
                       g_k, g_v, adj, qb, tid);
            CP_COMMIT;
            CP_WAIT1;
        } else {
            CP_WAIT0;
        }
        __syncthreads();

        const float* ks = kbuf[cur];
        const float* vs = vbuf[cur];
        const float* as_ = abuf[cur];

        // ----- scores (packed pairwise dims) -----
        unsigned long long s2[32];
#pragma unroll
        for (int j = 0; j < 32; j++) s2[j] = 0ull;
#pragma unroll
        for (int c = 0; c < 8; c++) {
            const int off = hb + (((c + h) & 7) << 2);
            unsigned long long qa = qpk[2 * c];
            unsigned long long qc = qpk[2 * c + 1];
#pragma unroll
            for (int j = 0; j < 32; j++) {
                ulonglong2 kv = *(const ulonglong2*)(ks + j * 256 + off);
                FMA2(s2[j], qa, kv.x);
                FMA2(s2[j], qc, kv.y);
            }
        }

        // ----- reduce pairs, mask, online softmax (log2 domain) -----
        float s[32];
        float mx = m;
#pragma unroll
        for (int j = 0; j < 32; j++) {
            float sv = f2_lo(s2[j]) + f2_hi(s2[j]);
            float e = as_[q * 40 + j];
            sv = (e > 0.f) ? sv : NEGL2;
            s[j] = sv;
            mx = fmaxf(mx, sv);
        }
        float corr = ex2(m - mx);
        m = mx;
        float ps = 0.f;
#pragma unroll
        for (int j = 0; j < 32; j++) {
            s[j] = ex2(s[j] - mx);
            ps += s[j];
        }
        l = l * corr + ps;
        {
            unsigned long long cd;
            PACK2(cd, corr, corr);
#pragma unroll
            for (int i = 0; i < 16; i++) MUL2(acc2[i], acc2[i], cd);
        }

        // ----- AV accumulate (packed) -----
#pragma unroll
        for (int j = 0; j < 32; j++) {
            unsigned long long pd;
            PACK2(pd, s[j], s[j]);
            const float* vr = vs + j * 256 + hb;
#pragma unroll
            for (int c = 0; c < 8; c++) {
                const int ro = ((c + h) & 7) << 2;
                ulonglong2 vv = *(const ulonglong2*)(vr + ro);
                FMA2(acc2[2 * c],     pd, vv.x);
                FMA2(acc2[2 * c + 1], pd, vv.y);
            }
        }

        __syncthreads();
    }

    // ----- epilogue -----
    float inv = 1.f / l;
    float* orow = g_att + (qb + q) * 256 + hb;
#pragma unroll
    for (int c = 0; c < 8; c++) {
        float4 o;
        o.x = f2_lo(acc2[2 * c]) * inv;
        o.y = f2_hi(acc2[2 * c]) * inv;
        o.z = f2_lo(acc2[2 * c + 1]) * inv;
        o.w = f2_hi(acc2[2 * c + 1]) * inv;
        *(float4*)(orow + (c << 2)) = o;
    }
}

// ---------------------------------------------------------------------------
extern "C" void kernel_launch(void* const* d_in, const int* in_sizes, int n_in,
                              void* d_out, int out_size)
{
    (void)in_sizes; (void)n_in; (void)out_size;
    const float* x   = (const float*)d_in[0];
    const float* adj = (const float*)d_in[1];
    const float* Wq  = (const float*)d_in[2];
    const float* bq  = (const float*)d_in[3];
    const float* Wk  = (const float*)d_in[4];
    const float* bk  = (const float*)d_in[5];
    const float* Wv  = (const float*)d_in[6];
    const float* bv  = (const float*)d_in[7];
    const float* Wo  = (const float*)d_in[8];
    const float* bo  = (const float*)d_in[9];
    float* out = (float*)d_out;

    float *pq, *pk, *pv, *pa;
    cudaGetSymbolAddress((void**)&pq, g_q);
    cudaGetSymbolAddress((void**)&pk, g_k);
    cudaGetSymbolAddress((void**)&pv, g_v);
    cudaGetSymbolAddress((void**)&pa, g_att);

    const int attn_smem = SM_FLOATS * 4;   // 141312 B
    cudaFuncSetAttribute(attn_kernel,
                         cudaFuncAttributeMaxDynamicSharedMemorySize, attn_smem);

    dim3 gg(64, 4);
    gemm_bias_kernel<<<gg, 256>>>(x, Wq, bq, pq);
    gemm_bias_kernel<<<gg, 256>>>(x, Wk, bk, pk);
    gemm_bias_kernel<<<gg, 256>>>(x, Wv, bv, pv);
    attn_kernel<<<128, 256, attn_smem>>>(adj);
    gemm_bias_kernel<<<gg, 256>>>(pa, Wo, bo, out);
}